// round 1
// baseline (speedup 1.0000x reference)
#include <cuda_runtime.h>
#include <cuda_bf16.h>
#include <cstdint>

#define HD   128
#define NMAX 100000
#define EPS  1e-5f

// ---------------- scratch (__device__ globals; no runtime allocation) ----------
__device__ int   g_deg[6 * NMAX];                       // [out0,in0,out1,in1,out2,in2] x N
__device__ float g_rs [6 * NMAX];                       // rsqrt(max(deg,1))
__device__ float g_agg[(size_t)3 * NMAX * HD];          // per-relation aggregation
__device__ float g_h  [(size_t)NMAX * HD];              // layer-0 output

// ---------------- small utility kernels ---------------------------------------
__global__ void zero_int_kernel(int* __restrict__ p, int count) {
    int i = blockIdx.x * blockDim.x + threadIdx.x;
    if (i < count) p[i] = 0;
}

__global__ void zero_f4_kernel(float4* __restrict__ p, int count4) {
    int i = blockIdx.x * blockDim.x + threadIdx.x;
    if (i < count4) p[i] = make_float4(0.f, 0.f, 0.f, 0.f);
}

__global__ void count_pair_kernel(const int* __restrict__ src, const int* __restrict__ dst,
                                  int* __restrict__ dout, int* __restrict__ din, int e) {
    int i = blockIdx.x * blockDim.x + threadIdx.x;
    if (i >= e) return;
    atomicAdd(dout + src[i], 1);
    atomicAdd(din  + dst[i], 1);
}

__global__ void rs_kernel(const int* __restrict__ deg, float* __restrict__ rs, int count) {
    int i = blockIdx.x * blockDim.x + threadIdx.x;
    if (i < count) {
        int d = deg[i];
        rs[i] = rsqrtf((float)(d < 1 ? 1 : d));
    }
}

// ---------------- scatter: agg[dst] += h[src] * rs_out[src] -------------------
// one warp per edge; lane handles 4 floats via float4 + vector RED
__global__ void scatter_kernel(const float* __restrict__ h,
                               const int* __restrict__ src, const int* __restrict__ dst,
                               const float* __restrict__ rs_out,
                               float* __restrict__ agg, int e) {
    long long gidx = (long long)blockIdx.x * blockDim.x + threadIdx.x;
    int eidx = (int)(gidx >> 5);
    int lane = (int)(gidx & 31);
    if (eidx >= e) return;
    int s = __ldg(src + eidx);
    int d = __ldg(dst + eidx);
    float sc = __ldg(rs_out + s);
    float4 v = __ldg((const float4*)(h + (size_t)s * HD) + lane);
    float4* ap = (float4*)(agg + (size_t)d * HD) + lane;
    asm volatile("red.global.add.v4.f32 [%0], {%1, %2, %3, %4};"
                 :: "l"(ap), "f"(v.x * sc), "f"(v.y * sc), "f"(v.z * sc), "f"(v.w * sc)
                 : "memory");
}

// ---------------- fused GEMM: out = BN(ReLU((sum_r (agg_r*rs_in_r) @ Wg_r + bg) @ Wfc + bfc))
// Block tile: 64 nodes x 128 outputs, 256 threads, each thread 4(m) x 8(n) accumulators.
// Phase-1 A is [64 x 384] (3 relations x 128 K each), staged 32 K at a time.
// Intermediate t stored to smem, then second GEMM (K=128) + epilogue.
__global__ __launch_bounds__(256) void gemm_fused_kernel(
    const float* __restrict__ agg,     // [3][n][HD]
    const float* __restrict__ rs0,     // rsqrt(in-deg) rel 0
    const float* __restrict__ rs1,
    const float* __restrict__ rs2,
    const float* __restrict__ Wg,      // [3][HD][HD]  (k-major rows)
    const float* __restrict__ bg,      // [3][HD]
    const float* __restrict__ Wfc,     // [HD][HD]
    const float* __restrict__ bfc,     // [HD]
    const float* __restrict__ gamma, const float* __restrict__ beta,
    const float* __restrict__ mean,  const float* __restrict__ var,
    float* __restrict__ out, int n)
{
    __shared__ float Ws[32 * HD];      // 16 KB weight tile
    __shared__ float Tb[64 * HD];      // 32 KB: phase-1 A-tile (as [64][36]) / phase-2 t

    const int tid = threadIdx.x;
    const int tn  = tid & 15;          // output-column group
    const int tm  = tid >> 4;          // node group
    const int jA  = tn * 4;            // columns [jA, jA+4)
    const int jB  = 64 + tn * 4;       // columns [jB, jB+4)   (split avoids LDS bank conflicts)
    const int m0  = tm * 4;
    const int bn0 = blockIdx.x * 64;

    // loader mappings
    const int lm = tid >> 2, kq = tid & 3;   // A: node lm, k-chunk kq*8
    const int kw = tid >> 3, jq = tid & 7;   // W: row kw, col-chunk jq*16
    const int gnode = bn0 + lm;

    float acc[4][8];
    #pragma unroll
    for (int jj = 0; jj < 8; jj++) {
        int j = (jj < 4) ? (jA + jj) : (jB + jj - 4);
        float b = __ldg(bg + j) + __ldg(bg + HD + j) + __ldg(bg + 2 * HD + j);
        #pragma unroll
        for (int i = 0; i < 4; i++) acc[i][jj] = b;
    }

    // ---------------- phase 1: t = sum_r (agg_r * rs_in_r) @ Wg_r + bg_sum ----
    for (int t = 0; t < 12; t++) {
        int r  = t >> 2;
        int kk = (t & 3) * 32;
        const float* rsr = (r == 0) ? rs0 : ((r == 1) ? rs1 : rs2);
        const float* Ar  = agg + (size_t)r * n * HD;

        __syncthreads();
        // stage A tile (scaled by rs_in at load)
        float4 v0 = make_float4(0.f, 0.f, 0.f, 0.f), v1 = v0;
        if (gnode < n) {
            const float4* p = (const float4*)(Ar + (size_t)gnode * HD + kk + kq * 8);
            v0 = __ldg(p); v1 = __ldg(p + 1);
            float s = __ldg(rsr + gnode);
            v0.x *= s; v0.y *= s; v0.z *= s; v0.w *= s;
            v1.x *= s; v1.y *= s; v1.z *= s; v1.w *= s;
        }
        float* as = &Tb[lm * 36 + kq * 8];
        *(float4*)(as)     = v0;
        *(float4*)(as + 4) = v1;
        // stage W tile
        {
            const float4* wp = (const float4*)(Wg + ((size_t)r * HD + kk + kw) * HD + jq * 16);
            float4 w0 = __ldg(wp), w1 = __ldg(wp + 1), w2 = __ldg(wp + 2), w3 = __ldg(wp + 3);
            float* ws = &Ws[kw * HD + jq * 16];
            *(float4*)(ws)      = w0;
            *(float4*)(ws + 4)  = w1;
            *(float4*)(ws + 8)  = w2;
            *(float4*)(ws + 12) = w3;
        }
        __syncthreads();

        #pragma unroll
        for (int k = 0; k < 32; k++) {
            float a0 = Tb[(m0 + 0) * 36 + k];
            float a1 = Tb[(m0 + 1) * 36 + k];
            float a2 = Tb[(m0 + 2) * 36 + k];
            float a3 = Tb[(m0 + 3) * 36 + k];
            float4 b0 = *(const float4*)&Ws[k * HD + jA];
            float4 b1 = *(const float4*)&Ws[k * HD + jB];
            acc[0][0] += a0 * b0.x; acc[0][1] += a0 * b0.y; acc[0][2] += a0 * b0.z; acc[0][3] += a0 * b0.w;
            acc[1][0] += a1 * b0.x; acc[1][1] += a1 * b0.y; acc[1][2] += a1 * b0.z; acc[1][3] += a1 * b0.w;
            acc[2][0] += a2 * b0.x; acc[2][1] += a2 * b0.y; acc[2][2] += a2 * b0.z; acc[2][3] += a2 * b0.w;
            acc[3][0] += a3 * b0.x; acc[3][1] += a3 * b0.y; acc[3][2] += a3 * b0.z; acc[3][3] += a3 * b0.w;
            acc[0][4] += a0 * b1.x; acc[0][5] += a0 * b1.y; acc[0][6] += a0 * b1.z; acc[0][7] += a0 * b1.w;
            acc[1][4] += a1 * b1.x; acc[1][5] += a1 * b1.y; acc[1][6] += a1 * b1.z; acc[1][7] += a1 * b1.w;
            acc[2][4] += a2 * b1.x; acc[2][5] += a2 * b1.y; acc[2][6] += a2 * b1.z; acc[2][7] += a2 * b1.w;
            acc[3][4] += a3 * b1.x; acc[3][5] += a3 * b1.y; acc[3][6] += a3 * b1.z; acc[3][7] += a3 * b1.w;
        }
    }

    // ---------------- write t into smem for second GEMM ----------------------
    __syncthreads();
    #pragma unroll
    for (int i = 0; i < 4; i++) {
        *(float4*)&Tb[(m0 + i) * HD + jA] = make_float4(acc[i][0], acc[i][1], acc[i][2], acc[i][3]);
        *(float4*)&Tb[(m0 + i) * HD + jB] = make_float4(acc[i][4], acc[i][5], acc[i][6], acc[i][7]);
    }

    float acc2[4][8];
    #pragma unroll
    for (int jj = 0; jj < 8; jj++) {
        int j = (jj < 4) ? (jA + jj) : (jB + jj - 4);
        float b = __ldg(bfc + j);
        #pragma unroll
        for (int i = 0; i < 4; i++) acc2[i][jj] = b;
    }

    // ---------------- phase 2: y = t @ Wfc + bfc ------------------------------
    for (int t = 0; t < 4; t++) {
        __syncthreads();
        {
            const float4* wp = (const float4*)(Wfc + ((size_t)t * 32 + kw) * HD + jq * 16);
            float4 w0 = __ldg(wp), w1 = __ldg(wp + 1), w2 = __ldg(wp + 2), w3 = __ldg(wp + 3);
            float* ws = &Ws[kw * HD + jq * 16];
            *(float4*)(ws)      = w0;
            *(float4*)(ws + 4)  = w1;
            *(float4*)(ws + 8)  = w2;
            *(float4*)(ws + 12) = w3;
        }
        __syncthreads();

        #pragma unroll
        for (int k = 0; k < 32; k++) {
            float a0 = Tb[(m0 + 0) * HD + t * 32 + k];
            float a1 = Tb[(m0 + 1) * HD + t * 32 + k];
            float a2 = Tb[(m0 + 2) * HD + t * 32 + k];
            float a3 = Tb[(m0 + 3) * HD + t * 32 + k];
            float4 b0 = *(const float4*)&Ws[k * HD + jA];
            float4 b1 = *(const float4*)&Ws[k * HD + jB];
            acc2[0][0] += a0 * b0.x; acc2[0][1] += a0 * b0.y; acc2[0][2] += a0 * b0.z; acc2[0][3] += a0 * b0.w;
            acc2[1][0] += a1 * b0.x; acc2[1][1] += a1 * b0.y; acc2[1][2] += a1 * b0.z; acc2[1][3] += a1 * b0.w;
            acc2[2][0] += a2 * b0.x; acc2[2][1] += a2 * b0.y; acc2[2][2] += a2 * b0.z; acc2[2][3] += a2 * b0.w;
            acc2[3][0] += a3 * b0.x; acc2[3][1] += a3 * b0.y; acc2[3][2] += a3 * b0.z; acc2[3][3] += a3 * b0.w;
            acc2[0][4] += a0 * b1.x; acc2[0][5] += a0 * b1.y; acc2[0][6] += a0 * b1.z; acc2[0][7] += a0 * b1.w;
            acc2[1][4] += a1 * b1.x; acc2[1][5] += a1 * b1.y; acc2[1][6] += a1 * b1.z; acc2[1][7] += a1 * b1.w;
            acc2[2][4] += a2 * b1.x; acc2[2][5] += a2 * b1.y; acc2[2][6] += a2 * b1.z; acc2[2][7] += a2 * b1.w;
            acc2[3][4] += a3 * b1.x; acc2[3][5] += a3 * b1.y; acc2[3][6] += a3 * b1.z; acc2[3][7] += a3 * b1.w;
        }
    }

    // ---------------- epilogue: ReLU + BatchNorm(eval) ------------------------
    #pragma unroll
    for (int jj = 0; jj < 8; jj++) {
        int j = (jj < 4) ? (jA + jj) : (jB + jj - 4);
        float sc = __ldg(gamma + j) * rsqrtf(__ldg(var + j) + EPS);
        float sh = __ldg(beta + j) - __ldg(mean + j) * sc;
        #pragma unroll
        for (int i = 0; i < 4; i++) {
            float y = fmaxf(acc2[i][jj], 0.f);
            acc2[i][jj] = y * sc + sh;
        }
    }
    #pragma unroll
    for (int i = 0; i < 4; i++) {
        int node = bn0 + m0 + i;
        if (node < n) {
            float* op = out + (size_t)node * HD;
            *(float4*)(op + jA) = make_float4(acc2[i][0], acc2[i][1], acc2[i][2], acc2[i][3]);
            *(float4*)(op + jB) = make_float4(acc2[i][4], acc2[i][5], acc2[i][6], acc2[i][7]);
        }
    }
}

// ---------------- launch --------------------------------------------------------
extern "C" void kernel_launch(void* const* d_in, const int* in_sizes, int n_in,
                              void* d_out, int out_size)
{
    const float* x     = (const float*)d_in[0];
    const int* srcs[3] = {(const int*)d_in[1], (const int*)d_in[3], (const int*)d_in[5]};
    const int* dsts[3] = {(const int*)d_in[2], (const int*)d_in[4], (const int*)d_in[6]};
    const float* Wgl[2] = {(const float*)d_in[7], (const float*)d_in[9]};
    const float* bgl[2] = {(const float*)d_in[8], (const float*)d_in[10]};
    const float* Wfc   = (const float*)d_in[11];
    const float* bfc   = (const float*)d_in[12];
    const float* gamma = (const float*)d_in[13];
    const float* beta  = (const float*)d_in[14];
    const float* mean  = (const float*)d_in[15];
    const float* var   = (const float*)d_in[16];

    int n = in_sizes[0] / HD;
    int es[3] = {in_sizes[1], in_sizes[3], in_sizes[5]};

    int*   p_deg; float *p_rs, *p_agg, *p_h;
    cudaGetSymbolAddress((void**)&p_deg, g_deg);
    cudaGetSymbolAddress((void**)&p_rs,  g_rs);
    cudaGetSymbolAddress((void**)&p_agg, g_agg);
    cudaGetSymbolAddress((void**)&p_h,   g_h);

    const int NT = 256;

    // degrees -> rsqrt normalizers (edges are inputs; recomputed every call)
    zero_int_kernel<<<(6 * n + NT - 1) / NT, NT>>>(p_deg, 6 * n);
    for (int r = 0; r < 3; r++)
        count_pair_kernel<<<(es[r] + NT - 1) / NT, NT>>>(
            srcs[r], dsts[r], p_deg + (size_t)2 * r * n, p_deg + (size_t)(2 * r + 1) * n, es[r]);
    rs_kernel<<<(6 * n + NT - 1) / NT, NT>>>(p_deg, p_rs, 6 * n);

    const float* hin = x;
    for (int layer = 0; layer < 2; layer++) {
        int nf4 = 3 * n * (HD / 4);
        zero_f4_kernel<<<(nf4 + NT - 1) / NT, NT>>>((float4*)p_agg, nf4);
        for (int r = 0; r < 3; r++) {
            long long thr = (long long)es[r] * 32;
            int blocks = (int)((thr + NT - 1) / NT);
            scatter_kernel<<<blocks, NT>>>(hin, srcs[r], dsts[r],
                                           p_rs + (size_t)2 * r * n,
                                           p_agg + (size_t)r * n * HD, es[r]);
        }
        float* outp = (layer == 0) ? p_h : (float*)d_out;
        gemm_fused_kernel<<<(n + 63) / 64, 256>>>(
            p_agg,
            p_rs + (size_t)1 * n, p_rs + (size_t)3 * n, p_rs + (size_t)5 * n,
            Wgl[layer], bgl[layer],
            Wfc + (size_t)layer * HD * HD, bfc + (size_t)layer * HD,
            gamma + (size_t)layer * HD, beta + (size_t)layer * HD,
            mean + (size_t)layer * HD, var + (size_t)layer * HD,
            outp, n);
        hin = p_h;
    }
}

// round 2
// speedup vs baseline: 1.7323x; 1.7323x over previous
#include <cuda_runtime.h>
#include <cuda_bf16.h>
#include <cstdint>

#define HD   128
#define NMAX 100000
#define EMAX 1700000
#define EPS  1e-5f

typedef unsigned long long ull;

// ---------------- scratch (__device__ globals; no runtime allocation) ----------
__device__ int   g_deg [6 * NMAX];                      // [out0,in0,out1,in1,out2,in2] x N
__device__ float g_rs  [6 * NMAX];                      // rsqrt(max(deg,1))
__device__ int   g_off [3 * (NMAX + 1)];                // CSR row offsets (by dst), per relation
__device__ int   g_cur [3 * NMAX];                      // fill cursors
__device__ int   g_csum[3 * 512];                       // chunk partial sums for scan
__device__ int   g_csr [3 * EMAX];                      // src ids sorted by dst
__device__ float g_agg [(size_t)3 * NMAX * HD];         // per-relation normalized aggregation
__device__ float g_h   [(size_t)NMAX * HD];             // layer-0 output

// ---------------- f32x2 helpers (sm_103a packed fp32) ---------------------------
__device__ __forceinline__ ull pack2(float a) {
    ull r; asm("mov.b64 %0, {%1, %1};" : "=l"(r) : "f"(a)); return r;
}
__device__ __forceinline__ ull pack2f(float lo, float hi) {
    ull r; asm("mov.b64 %0, {%1, %2};" : "=l"(r) : "f"(lo), "f"(hi)); return r;
}
__device__ __forceinline__ float2 unpack2(ull v) {
    float2 r; asm("mov.b64 {%0, %1}, %2;" : "=f"(r.x), "=f"(r.y) : "l"(v)); return r;
}
__device__ __forceinline__ void fma2(ull& d, ull a, ull b) {
    asm("fma.rn.f32x2 %0, %1, %2, %0;" : "+l"(d) : "l"(a), "l"(b));
}

// ---------------- small utility kernels ---------------------------------------
__global__ void zero_int_kernel(int* __restrict__ p, int count) {
    int i = blockIdx.x * blockDim.x + threadIdx.x;
    if (i < count) p[i] = 0;
}

__global__ void count_pair_kernel(const int* __restrict__ src, const int* __restrict__ dst,
                                  int* __restrict__ dout, int* __restrict__ din, int e) {
    int i = blockIdx.x * blockDim.x + threadIdx.x;
    if (i >= e) return;
    atomicAdd(dout + src[i], 1);
    atomicAdd(din  + dst[i], 1);
}

__global__ void rs_kernel(const int* __restrict__ deg, float* __restrict__ rs, int count) {
    int i = blockIdx.x * blockDim.x + threadIdx.x;
    if (i < count) {
        int d = deg[i];
        rs[i] = rsqrtf((float)(d < 1 ? 1 : d));
    }
}

// ---------------- CSR build: 2-level exclusive scan + bucket fill --------------
__global__ void chunk_sum_kernel(const int* __restrict__ deg, int* __restrict__ csum, int n) {
    __shared__ int s[256];
    int i = blockIdx.x * 256 + threadIdx.x;
    s[threadIdx.x] = (i < n) ? deg[i] : 0;
    __syncthreads();
    #pragma unroll
    for (int st = 128; st > 0; st >>= 1) {
        if (threadIdx.x < st) s[threadIdx.x] += s[threadIdx.x + st];
        __syncthreads();
    }
    if (threadIdx.x == 0) csum[blockIdx.x] = s[0];
}

__global__ void scan_chunks_kernel(int* __restrict__ csum, int nc) {
    __shared__ int s[512];
    int t = threadIdx.x;
    int v0 = (t < nc) ? csum[t] : 0;
    s[t] = v0;
    __syncthreads();
    #pragma unroll
    for (int off = 1; off < 512; off <<= 1) {
        int v = (t >= off) ? s[t - off] : 0;
        __syncthreads();
        s[t] += v;
        __syncthreads();
    }
    if (t < nc) csum[t] = s[t] - v0;   // exclusive
}

__global__ void write_offsets_kernel(const int* __restrict__ deg, const int* __restrict__ csum,
                                     int* __restrict__ off, int* __restrict__ cur, int n) {
    __shared__ int s[256];
    int t = threadIdx.x;
    int i = blockIdx.x * 256 + t;
    int d = (i < n) ? deg[i] : 0;
    s[t] = d;
    __syncthreads();
    #pragma unroll
    for (int o = 1; o < 256; o <<= 1) {
        int v = (t >= o) ? s[t - o] : 0;
        __syncthreads();
        s[t] += v;
        __syncthreads();
    }
    int excl = s[t] - d + csum[blockIdx.x];
    if (i < n) {
        off[i] = excl;
        cur[i] = excl;
        if (i == n - 1) off[n] = excl + d;
    }
}

__global__ void csr_fill_kernel(const int* __restrict__ src, const int* __restrict__ dst,
                                int* __restrict__ cur, int* __restrict__ csr, int e) {
    int i = blockIdx.x * blockDim.x + threadIdx.x;
    if (i >= e) return;
    int slot = atomicAdd(cur + dst[i], 1);
    csr[slot] = src[i];
}

// ---------------- gather aggregation: agg[d] = rs_in[d] * sum_e rs_out[s] h[s] --
// one warp per dst node, lane handles 4 floats (float4)
__global__ void gather_kernel(const float* __restrict__ h,
                              const int* __restrict__ csr, const int* __restrict__ off,
                              const float* __restrict__ rs_out, const float* __restrict__ rs_in,
                              float* __restrict__ agg, int n) {
    int w    = (blockIdx.x * blockDim.x + threadIdx.x) >> 5;
    int lane = threadIdx.x & 31;
    if (w >= n) return;
    int e0 = __ldg(off + w), e1 = __ldg(off + w + 1);
    float4 acc = make_float4(0.f, 0.f, 0.f, 0.f);
    int e = e0;
    for (; e + 1 < e1; e += 2) {
        int sa = __ldg(csr + e), sb = __ldg(csr + e + 1);
        float ca = __ldg(rs_out + sa), cb = __ldg(rs_out + sb);
        float4 va = __ldg((const float4*)(h + (size_t)sa * HD) + lane);
        float4 vb = __ldg((const float4*)(h + (size_t)sb * HD) + lane);
        acc.x = fmaf(va.x, ca, acc.x); acc.y = fmaf(va.y, ca, acc.y);
        acc.z = fmaf(va.z, ca, acc.z); acc.w = fmaf(va.w, ca, acc.w);
        acc.x = fmaf(vb.x, cb, acc.x); acc.y = fmaf(vb.y, cb, acc.y);
        acc.z = fmaf(vb.z, cb, acc.z); acc.w = fmaf(vb.w, cb, acc.w);
    }
    if (e < e1) {
        int sa = __ldg(csr + e);
        float ca = __ldg(rs_out + sa);
        float4 va = __ldg((const float4*)(h + (size_t)sa * HD) + lane);
        acc.x = fmaf(va.x, ca, acc.x); acc.y = fmaf(va.y, ca, acc.y);
        acc.z = fmaf(va.z, ca, acc.z); acc.w = fmaf(va.w, ca, acc.w);
    }
    float ri = __ldg(rs_in + w);
    acc.x *= ri; acc.y *= ri; acc.z *= ri; acc.w *= ri;
    ((float4*)(agg + (size_t)w * HD))[lane] = acc;
}

// ---------------- fused GEMM (f32x2): out = BN(ReLU((sum_r agg_r @ Wg_r + bg) @ Wfc + bfc))
// Block tile 64 nodes x 128 outputs, 256 threads, each thread 4(m) x 8(n) via f32x2 pairs.
__global__ __launch_bounds__(256) void gemm_fused_kernel(
    const float* __restrict__ agg,     // [3][n][HD], already fully normalized
    const float* __restrict__ Wg,      // [3][HD][HD]
    const float* __restrict__ bg,      // [3][HD]
    const float* __restrict__ Wfc,     // [HD][HD]
    const float* __restrict__ bfc,     // [HD]
    const float* __restrict__ gamma, const float* __restrict__ beta,
    const float* __restrict__ mean,  const float* __restrict__ var,
    float* __restrict__ out, int n)
{
    __shared__ alignas(16) float Ws[32 * HD];   // 16 KB weight tile
    __shared__ alignas(16) float Tb[64 * HD];   // 32 KB: phase-1 A-tile ([64][36]) / phase-2 t

    const int tid = threadIdx.x;
    const int tn  = tid & 15;
    const int tm  = tid >> 4;
    const int jA  = tn * 4;
    const int jB  = 64 + tn * 4;
    const int m0  = tm * 4;
    const int bn0 = blockIdx.x * 64;

    const int lm = tid >> 2, kq = tid & 3;   // A loader: node lm, k-chunk kq*8
    const int kw = tid >> 3, jq = tid & 7;   // W loader: row kw, col-chunk jq*16
    const int gnode = bn0 + lm;

    // acc pairs: [m][pair]; pairs 0,1 cover jA..jA+3; pairs 2,3 cover jB..jB+3
    ull acc[4][4];
    #pragma unroll
    for (int p = 0; p < 4; p++) {
        int j = (p < 2) ? (jA + p * 2) : (jB + (p - 2) * 2);
        float blo = __ldg(bg + j)     + __ldg(bg + HD + j)     + __ldg(bg + 2 * HD + j);
        float bhi = __ldg(bg + j + 1) + __ldg(bg + HD + j + 1) + __ldg(bg + 2 * HD + j + 1);
        ull b = pack2f(blo, bhi);
        #pragma unroll
        for (int i = 0; i < 4; i++) acc[i][p] = b;
    }

    // ---------------- phase 1: t = sum_r agg_r @ Wg_r + bg_sum ----------------
    for (int t = 0; t < 12; t++) {
        int r  = t >> 2;
        int kk = (t & 3) * 32;
        const float* Ar = agg + (size_t)r * n * HD;

        __syncthreads();
        float4 v0 = make_float4(0.f, 0.f, 0.f, 0.f), v1 = v0;
        if (gnode < n) {
            const float4* p = (const float4*)(Ar + (size_t)gnode * HD + kk + kq * 8);
            v0 = __ldg(p); v1 = __ldg(p + 1);
        }
        float* as = &Tb[lm * 36 + kq * 8];
        *(float4*)(as)     = v0;
        *(float4*)(as + 4) = v1;
        {
            const float4* wp = (const float4*)(Wg + ((size_t)r * HD + kk + kw) * HD + jq * 16);
            float4 w0 = __ldg(wp), w1 = __ldg(wp + 1), w2 = __ldg(wp + 2), w3 = __ldg(wp + 3);
            float* ws = &Ws[kw * HD + jq * 16];
            *(float4*)(ws)      = w0;
            *(float4*)(ws + 4)  = w1;
            *(float4*)(ws + 8)  = w2;
            *(float4*)(ws + 12) = w3;
        }
        __syncthreads();

        #pragma unroll
        for (int k = 0; k < 32; k++) {
            ull p0 = pack2(Tb[(m0 + 0) * 36 + k]);
            ull p1 = pack2(Tb[(m0 + 1) * 36 + k]);
            ull p2 = pack2(Tb[(m0 + 2) * 36 + k]);
            ull p3 = pack2(Tb[(m0 + 3) * 36 + k]);
            ulonglong2 b0 = *(const ulonglong2*)&Ws[k * HD + jA];
            ulonglong2 b1 = *(const ulonglong2*)&Ws[k * HD + jB];
            fma2(acc[0][0], p0, b0.x); fma2(acc[0][1], p0, b0.y); fma2(acc[0][2], p0, b1.x); fma2(acc[0][3], p0, b1.y);
            fma2(acc[1][0], p1, b0.x); fma2(acc[1][1], p1, b0.y); fma2(acc[1][2], p1, b1.x); fma2(acc[1][3], p1, b1.y);
            fma2(acc[2][0], p2, b0.x); fma2(acc[2][1], p2, b0.y); fma2(acc[2][2], p2, b1.x); fma2(acc[2][3], p2, b1.y);
            fma2(acc[3][0], p3, b0.x); fma2(acc[3][1], p3, b0.y); fma2(acc[3][2], p3, b1.x); fma2(acc[3][3], p3, b1.y);
        }
    }

    // ---------------- write t into smem for second GEMM ----------------------
    __syncthreads();
    #pragma unroll
    for (int i = 0; i < 4; i++) {
        float2 u0 = unpack2(acc[i][0]), u1 = unpack2(acc[i][1]);
        float2 u2 = unpack2(acc[i][2]), u3 = unpack2(acc[i][3]);
        *(float4*)&Tb[(m0 + i) * HD + jA] = make_float4(u0.x, u0.y, u1.x, u1.y);
        *(float4*)&Tb[(m0 + i) * HD + jB] = make_float4(u2.x, u2.y, u3.x, u3.y);
    }

    ull acc2[4][4];
    #pragma unroll
    for (int p = 0; p < 4; p++) {
        int j = (p < 2) ? (jA + p * 2) : (jB + (p - 2) * 2);
        ull b = pack2f(__ldg(bfc + j), __ldg(bfc + j + 1));
        #pragma unroll
        for (int i = 0; i < 4; i++) acc2[i][p] = b;
    }

    // ---------------- phase 2: y = t @ Wfc + bfc ------------------------------
    for (int t = 0; t < 4; t++) {
        __syncthreads();
        {
            const float4* wp = (const float4*)(Wfc + ((size_t)t * 32 + kw) * HD + jq * 16);
            float4 w0 = __ldg(wp), w1 = __ldg(wp + 1), w2 = __ldg(wp + 2), w3 = __ldg(wp + 3);
            float* ws = &Ws[kw * HD + jq * 16];
            *(float4*)(ws)      = w0;
            *(float4*)(ws + 4)  = w1;
            *(float4*)(ws + 8)  = w2;
            *(float4*)(ws + 12) = w3;
        }
        __syncthreads();

        #pragma unroll
        for (int k = 0; k < 32; k++) {
            ull p0 = pack2(Tb[(m0 + 0) * HD + t * 32 + k]);
            ull p1 = pack2(Tb[(m0 + 1) * HD + t * 32 + k]);
            ull p2 = pack2(Tb[(m0 + 2) * HD + t * 32 + k]);
            ull p3 = pack2(Tb[(m0 + 3) * HD + t * 32 + k]);
            ulonglong2 b0 = *(const ulonglong2*)&Ws[k * HD + jA];
            ulonglong2 b1 = *(const ulonglong2*)&Ws[k * HD + jB];
            fma2(acc2[0][0], p0, b0.x); fma2(acc2[0][1], p0, b0.y); fma2(acc2[0][2], p0, b1.x); fma2(acc2[0][3], p0, b1.y);
            fma2(acc2[1][0], p1, b0.x); fma2(acc2[1][1], p1, b0.y); fma2(acc2[1][2], p1, b1.x); fma2(acc2[1][3], p1, b1.y);
            fma2(acc2[2][0], p2, b0.x); fma2(acc2[2][1], p2, b0.y); fma2(acc2[2][2], p2, b1.x); fma2(acc2[2][3], p2, b1.y);
            fma2(acc2[3][0], p3, b0.x); fma2(acc2[3][1], p3, b0.y); fma2(acc2[3][2], p3, b1.x); fma2(acc2[3][3], p3, b1.y);
        }
    }

    // ---------------- epilogue: ReLU + BatchNorm(eval) ------------------------
    float res[4][8];
    #pragma unroll
    for (int p = 0; p < 4; p++) {
        int j = (p < 2) ? (jA + p * 2) : (jB + (p - 2) * 2);
        float sc0 = __ldg(gamma + j)     * rsqrtf(__ldg(var + j)     + EPS);
        float sc1 = __ldg(gamma + j + 1) * rsqrtf(__ldg(var + j + 1) + EPS);
        float sh0 = __ldg(beta + j)     - __ldg(mean + j)     * sc0;
        float sh1 = __ldg(beta + j + 1) - __ldg(mean + j + 1) * sc1;
        #pragma unroll
        for (int i = 0; i < 4; i++) {
            float2 u = unpack2(acc2[i][p]);
            res[i][p * 2]     = fmaxf(u.x, 0.f) * sc0 + sh0;
            res[i][p * 2 + 1] = fmaxf(u.y, 0.f) * sc1 + sh1;
        }
    }
    #pragma unroll
    for (int i = 0; i < 4; i++) {
        int node = bn0 + m0 + i;
        if (node < n) {
            float* op = out + (size_t)node * HD;
            *(float4*)(op + jA) = make_float4(res[i][0], res[i][1], res[i][2], res[i][3]);
            *(float4*)(op + jB) = make_float4(res[i][4], res[i][5], res[i][6], res[i][7]);
        }
    }
}

// ---------------- launch --------------------------------------------------------
extern "C" void kernel_launch(void* const* d_in, const int* in_sizes, int n_in,
                              void* d_out, int out_size)
{
    const float* x     = (const float*)d_in[0];
    const int* srcs[3] = {(const int*)d_in[1], (const int*)d_in[3], (const int*)d_in[5]};
    const int* dsts[3] = {(const int*)d_in[2], (const int*)d_in[4], (const int*)d_in[6]};
    const float* Wgl[2] = {(const float*)d_in[7], (const float*)d_in[9]};
    const float* bgl[2] = {(const float*)d_in[8], (const float*)d_in[10]};
    const float* Wfc   = (const float*)d_in[11];
    const float* bfc   = (const float*)d_in[12];
    const float* gamma = (const float*)d_in[13];
    const float* beta  = (const float*)d_in[14];
    const float* mean  = (const float*)d_in[15];
    const float* var   = (const float*)d_in[16];

    int n = in_sizes[0] / HD;
    int es[3] = {in_sizes[1], in_sizes[3], in_sizes[5]};

    int *p_deg, *p_off, *p_cur, *p_csum, *p_csr;
    float *p_rs, *p_agg, *p_h;
    cudaGetSymbolAddress((void**)&p_deg,  g_deg);
    cudaGetSymbolAddress((void**)&p_rs,   g_rs);
    cudaGetSymbolAddress((void**)&p_off,  g_off);
    cudaGetSymbolAddress((void**)&p_cur,  g_cur);
    cudaGetSymbolAddress((void**)&p_csum, g_csum);
    cudaGetSymbolAddress((void**)&p_csr,  g_csr);
    cudaGetSymbolAddress((void**)&p_agg,  g_agg);
    cudaGetSymbolAddress((void**)&p_h,    g_h);

    const int NT = 256;
    const int nchunks = (n + 255) / 256;

    // 1) degrees
    zero_int_kernel<<<(6 * n + NT - 1) / NT, NT>>>(p_deg, 6 * n);
    for (int r = 0; r < 3; r++)
        count_pair_kernel<<<(es[r] + NT - 1) / NT, NT>>>(
            srcs[r], dsts[r], p_deg + (size_t)2 * r * n, p_deg + (size_t)(2 * r + 1) * n, es[r]);
    rs_kernel<<<(6 * n + NT - 1) / NT, NT>>>(p_deg, p_rs, 6 * n);

    // 2) CSR by dst, per relation (reused by both layers)
    for (int r = 0; r < 3; r++) {
        const int* deg_in = p_deg + (size_t)(2 * r + 1) * n;
        int* off  = p_off  + (size_t)r * (NMAX + 1);
        int* cur  = p_cur  + (size_t)r * NMAX;
        int* csum = p_csum + (size_t)r * 512;
        int* csr  = p_csr  + (size_t)r * EMAX;
        chunk_sum_kernel<<<nchunks, 256>>>(deg_in, csum, n);
        scan_chunks_kernel<<<1, 512>>>(csum, nchunks);
        write_offsets_kernel<<<nchunks, 256>>>(deg_in, csum, off, cur, n);
        csr_fill_kernel<<<(es[r] + NT - 1) / NT, NT>>>(srcs[r], dsts[r], cur, csr, es[r]);
    }

    // 3) layers
    const float* hin = x;
    for (int layer = 0; layer < 2; layer++) {
        for (int r = 0; r < 3; r++) {
            long long thr = (long long)n * 32;
            int blocks = (int)((thr + NT - 1) / NT);
            gather_kernel<<<blocks, NT>>>(hin,
                                          p_csr + (size_t)r * EMAX,
                                          p_off + (size_t)r * (NMAX + 1),
                                          p_rs + (size_t)2 * r * n,        // rs_out
                                          p_rs + (size_t)(2 * r + 1) * n,  // rs_in
                                          p_agg + (size_t)r * n * HD, n);
        }
        float* outp = (layer == 0) ? p_h : (float*)d_out;
        gemm_fused_kernel<<<(n + 63) / 64, 256>>>(
            p_agg,
            Wgl[layer], bgl[layer],
            Wfc + (size_t)layer * HD * HD, bfc + (size_t)layer * HD,
            gamma + (size_t)layer * HD, beta + (size_t)layer * HD,
            mean + (size_t)layer * HD, var + (size_t)layer * HD,
            outp, n);
        hin = p_h;
    }
}